// round 15
// baseline (speedup 1.0000x reference)
#include <cuda_runtime.h>
#include <math.h>

// Fixed geometry: D=128, H=8, PAGE_SIZE=16, STREAMING_BUDGET=4096, NUM_SINK=4.
#define DD      128
#define HH      8
#define PAGE    16
#define BUDGET  4096
#define SINK    4
#define VEC_PER_ROW (DD/4)            // 32 float4 per head-row
#define F4_PER_PAGE (2*PAGE*HH*DD/4)  // 8192 float4 per page (k half then v half)

// log2(10000)/64, double precision
#define LOG2_1E4_OVER_64 0.20762050593045952

// Source head-row pointer for the streaming-gather (kv = 0 keys / 1 values).
__device__ __forceinline__ const float4*
resolve_row(const float4* __restrict__ cache, const float4* __restrict__ fresh,
            int b, int p, int kv, int ctx, int ql, int maxkv, int seq_len)
{
    bool active  = (ql > 0);
    bool rolling = active && (ctx + ql >  BUDGET);
    bool plain   = active && (ctx + ql <= BUDGET);

    if (rolling && p >= SINK && p < BUDGET - ql) {
        int srs = min(ctx, BUDGET) - (BUDGET - ql - SINK);
        int pos = min(max(p + srs - SINK, 0), maxkv - 1);
        int gp  = b * maxkv + pos;
        return cache + (size_t)(gp >> 4) * F4_PER_PAGE
                     + (size_t)(kv * PAGE + (gp & 15)) * (HH * VEC_PER_ROW);
    }
    if ((rolling && p >= BUDGET - ql && p < BUDGET) ||
        (plain   && p >= ctx         && p < ctx + ql)) {
        int sp = rolling ? (p - (BUDGET - ql)) : (p - ctx);
        sp = min(max(sp, 0), seq_len - 1);
        return fresh + ((size_t)(b * seq_len + sp) * HH) * VEC_PER_ROW;
    }
    int gp = b * maxkv + p;
    return cache + (size_t)(gp >> 4) * F4_PER_PAGE
                 + (size_t)(kv * PAGE + (gp & 15)) * (HH * VEC_PER_ROW);
}

// Destination float4 base of position (b,p,kv) in the paged output (head 0).
__device__ __forceinline__ size_t out_row_base(int b, int p, int kv, int maxkv)
{
    int gp = b * maxkv + p;
    return (size_t)(gp >> 4) * F4_PER_PAGE
         + (size_t)(kv * PAGE + (gp & 15)) * (HH * VEC_PER_ROW);
}

// Fused single-launch kernel. Flat grid over three regions:
//   [0, nA)        rope'd keys, p<BUDGET. thread = float4 pair (d4, d4+16).
//   [nA, nAV)      value gather, p<BUDGET. thread = 2 consecutive float4.
//   [nAV, ntot)    identity copy, p>=BUDGET: thread = 4 float4 at strides
//                  {0,32,64,96} in a 128-f4 group -> warp-contiguous, MLP 4.
// Stores are write-through (__stwt): output is write-once, never re-read.
// Identity loads are evict-first (__ldcs): strictly one-touch, preserves the
// L2 reuse window of the gather phase.
__global__ __launch_bounds__(256)
void skv_fused(const float4* __restrict__ cache,
               const float4* __restrict__ knew,
               const float4* __restrict__ vnew,
               const int*    __restrict__ qlens,
               const int*    __restrict__ ctxp,
               float4*       __restrict__ out,
               int maxkv, int seq_len,
               int nA, int nAV,
               int id_shift, int id_mask, int ntot)
{
    __shared__ float sfreq[DD/2];
    int tid = threadIdx.x;
    int gid = blockIdx.x * 256 + tid;
    int blk0 = blockIdx.x * 256;

    // Blocks overlapping the rope region build the inv_freq table in smem
    // (double exp2 -> correctly-rounded fp32, same values as a double pow).
    if (blk0 < nA) {
        if (tid < DD/2)
            sfreq[tid] = (float)exp2(-(double)tid * LOG2_1E4_OVER_64);
        __syncthreads();
    }

    if (gid >= ntot) return;

    if (gid < nA) {
        // ---- RoPE keys ----
        int d4 = gid & 15;                 // lower-half float4 index (0..15)
        int h  = (gid >> 4) & (HH - 1);
        int p  = (gid >> 7) & (BUDGET - 1);
        int b  = gid >> 19;

        int ctx = *ctxp;
        int ql  = __ldg(&qlens[b]);

        const float4* row = resolve_row(cache, knew, b, p, 0, ctx, ql, maxkv, seq_len)
                            + h * VEC_PER_ROW;
        float4 x1 = __ldg(&row[d4]);
        float4 x2 = __ldg(&row[d4 + 16]);

        float fp = (float)p;
        int i0 = d4 * 4;
        float4 lo, hi;
        const float* a  = (const float*)&x1;
        const float* bb = (const float*)&x2;
        float* lf = (float*)&lo;
        float* hf = (float*)&hi;
        #pragma unroll
        for (int j = 0; j < 4; j++) {
            float s, c;
            __sincosf(fp * sfreq[i0 + j], &s, &c);   // MUFU fast path
            lf[j] = a[j] * c - bb[j] * s;
            hf[j] = a[j] * s + bb[j] * c;
        }

        float4* orow = out + out_row_base(b, p, 0, maxkv) + h * VEC_PER_ROW;
        __stwt(&orow[d4],      lo);
        __stwt(&orow[d4 + 16], hi);
    } else if (gid < nAV) {
        // ---- value gather, p < BUDGET ----
        int j  = gid - nA;
        int d4 = (j & 15) * 2;             // pair of consecutive float4
        int h  = (j >> 4) & (HH - 1);
        int p  = (j >> 7) & (BUDGET - 1);
        int b  = j >> 19;

        int ctx = *ctxp;
        int ql  = __ldg(&qlens[b]);
        const float4* row = resolve_row(cache, vnew, b, p, 1, ctx, ql, maxkv, seq_len)
                            + h * VEC_PER_ROW;
        float4 v0 = __ldg(&row[d4]);
        float4 v1 = __ldg(&row[d4 + 1]);
        float4* orow = out + out_row_base(b, p, 1, maxkv) + h * VEC_PER_ROW;
        __stwt(&orow[d4],     v0);
        __stwt(&orow[d4 + 1], v1);
    } else {
        // ---- identity region: 4 warp-contiguous units, MLP 4, one-touch ----
        int j = gid - nAV;
        int b = j >> id_shift;
        int w = j & id_mask;               // per-batch thread index
        long long base = ((long long)b * (maxkv / PAGE) + (BUDGET / PAGE))
                         * F4_PER_PAGE;
        // group of 128 f4 per 32 threads; thread owns lanes {0,32,64,96}+lane
        long long idx = base + (long long)(w >> 5) * 128 + (w & 31);
        float4 v0 = __ldcs(&cache[idx]);
        float4 v1 = __ldcs(&cache[idx + 32]);
        float4 v2 = __ldcs(&cache[idx + 64]);
        float4 v3 = __ldcs(&cache[idx + 96]);
        __stwt(&out[idx],      v0);
        __stwt(&out[idx + 32], v1);
        __stwt(&out[idx + 64], v2);
        __stwt(&out[idx + 96], v3);
    }
}

extern "C" void kernel_launch(void* const* d_in, const int* in_sizes, int n_in,
                              void* d_out, int out_size) {
    const float4* cache = (const float4*)d_in[0];
    const float4* knew  = (const float4*)d_in[1];
    const float4* vnew  = (const float4*)d_in[2];
    const int*    qlens = (const int*)d_in[3];
    const int*    ctxp  = (const int*)d_in[5];   // context_len scalar (device)

    int bsz = in_sizes[3];
    int total_pos = in_sizes[0] / (2 * HH * DD);
    int maxkv = total_pos / bsz;                 // 8192
    int seq_len = in_sizes[1] / (bsz * HH * DD); // 2048

    // Region sizes (threads)
    int nA  = bsz * BUDGET * HH * (VEC_PER_ROW / 2);   // rope pairs
    int nV  = bsz * BUDGET * HH * (VEC_PER_ROW / 2);   // value 32B units
    int nAV = nA + nV;

    int id_pages = maxkv / PAGE - BUDGET / PAGE;                 // per batch
    long long id_thr = (long long)id_pages * F4_PER_PAGE / 4;    // threads/batch (pow2)
    int id_shift = 0;
    while ((1LL << id_shift) < id_thr) id_shift++;
    int id_mask = (int)(id_thr - 1);

    int ntot = nAV + (int)(id_thr * bsz);
    int blocks = (ntot + 255) / 256;

    skv_fused<<<blocks, 256>>>(cache, knew, vnew, qlens, ctxp,
                               (float4*)d_out, maxkv, seq_len,
                               nA, nAV, id_shift, id_mask, ntot);
}

// round 16
// speedup vs baseline: 1.0048x; 1.0048x over previous
#include <cuda_runtime.h>
#include <math.h>

// Fixed geometry: D=128, H=8, PAGE_SIZE=16, STREAMING_BUDGET=4096, NUM_SINK=4.
#define DD      128
#define HH      8
#define PAGE    16
#define BUDGET  4096
#define SINK    4
#define VEC_PER_ROW (DD/4)            // 32 float4 per head-row
#define F4_PER_PAGE (2*PAGE*HH*DD/4)  // 8192 float4 per page (k half then v half)

// log2(10000)/64, double precision
#define LOG2_1E4_OVER_64 0.20762050593045952

// Source head-row pointer for the streaming-gather (kv = 0 keys / 1 values).
__device__ __forceinline__ const float4*
resolve_row(const float4* __restrict__ cache, const float4* __restrict__ fresh,
            int b, int p, int kv, int ctx, int ql, int maxkv, int seq_len)
{
    bool active  = (ql > 0);
    bool rolling = active && (ctx + ql >  BUDGET);
    bool plain   = active && (ctx + ql <= BUDGET);

    if (rolling && p >= SINK && p < BUDGET - ql) {
        int srs = min(ctx, BUDGET) - (BUDGET - ql - SINK);
        int pos = min(max(p + srs - SINK, 0), maxkv - 1);
        int gp  = b * maxkv + pos;
        return cache + (size_t)(gp >> 4) * F4_PER_PAGE
                     + (size_t)(kv * PAGE + (gp & 15)) * (HH * VEC_PER_ROW);
    }
    if ((rolling && p >= BUDGET - ql && p < BUDGET) ||
        (plain   && p >= ctx         && p < ctx + ql)) {
        int sp = rolling ? (p - (BUDGET - ql)) : (p - ctx);
        sp = min(max(sp, 0), seq_len - 1);
        return fresh + ((size_t)(b * seq_len + sp) * HH) * VEC_PER_ROW;
    }
    int gp = b * maxkv + p;
    return cache + (size_t)(gp >> 4) * F4_PER_PAGE
                 + (size_t)(kv * PAGE + (gp & 15)) * (HH * VEC_PER_ROW);
}

// Destination float4 base of position (b,p,kv) in the paged output (head 0).
__device__ __forceinline__ size_t out_row_base(int b, int p, int kv, int maxkv)
{
    int gp = b * maxkv + p;
    return (size_t)(gp >> 4) * F4_PER_PAGE
         + (size_t)(kv * PAGE + (gp & 15)) * (HH * VEC_PER_ROW);
}

// Fused single-launch kernel. Flat grid over three regions:
//   [0, nA)        rope'd keys, p<BUDGET. thread = float4 pair (d4, d4+16).
//   [nA, nAV)      value gather, p<BUDGET. thread = 2 consecutive float4.
//   [nAV, ntot)    identity copy, p>=BUDGET: thread = 4 float4 at strides
//                  {0,32,64,96} in a 128-f4 group -> warp-contiguous, MLP 4.
// All output stores are write-through (__stwt) — output is write-once,
// never re-read; keeps L2 for gather-read reuse, steadier DRAM write stream.
__global__ __launch_bounds__(256)
void skv_fused(const float4* __restrict__ cache,
               const float4* __restrict__ knew,
               const float4* __restrict__ vnew,
               const int*    __restrict__ qlens,
               const int*    __restrict__ ctxp,
               float4*       __restrict__ out,
               int maxkv, int seq_len,
               int nA, int nAV,
               int id_shift, int id_mask, int ntot)
{
    __shared__ float sfreq[DD/2];
    int tid = threadIdx.x;
    int gid = blockIdx.x * 256 + tid;
    int blk0 = blockIdx.x * 256;

    // Blocks overlapping the rope region build the inv_freq table in smem
    // (double exp2 -> correctly-rounded fp32, same values as a double pow).
    if (blk0 < nA) {
        if (tid < DD/2)
            sfreq[tid] = (float)exp2(-(double)tid * LOG2_1E4_OVER_64);
        __syncthreads();
    }

    if (gid >= ntot) return;

    if (gid < nA) {
        // ---- RoPE keys ----
        int d4 = gid & 15;                 // lower-half float4 index (0..15)
        int h  = (gid >> 4) & (HH - 1);
        int p  = (gid >> 7) & (BUDGET - 1);
        int b  = gid >> 19;

        int ctx = *ctxp;
        int ql  = __ldg(&qlens[b]);

        const float4* row = resolve_row(cache, knew, b, p, 0, ctx, ql, maxkv, seq_len)
                            + h * VEC_PER_ROW;
        float4 x1 = __ldg(&row[d4]);
        float4 x2 = __ldg(&row[d4 + 16]);

        float fp = (float)p;
        int i0 = d4 * 4;
        float4 lo, hi;
        const float* a  = (const float*)&x1;
        const float* bb = (const float*)&x2;
        float* lf = (float*)&lo;
        float* hf = (float*)&hi;
        #pragma unroll
        for (int j = 0; j < 4; j++) {
            float s, c;
            __sincosf(fp * sfreq[i0 + j], &s, &c);   // MUFU fast path
            lf[j] = a[j] * c - bb[j] * s;
            hf[j] = a[j] * s + bb[j] * c;
        }

        float4* orow = out + out_row_base(b, p, 0, maxkv) + h * VEC_PER_ROW;
        __stwt(&orow[d4],      lo);
        __stwt(&orow[d4 + 16], hi);
    } else if (gid < nAV) {
        // ---- value gather, p < BUDGET ----
        int j  = gid - nA;
        int d4 = (j & 15) * 2;             // pair of consecutive float4
        int h  = (j >> 4) & (HH - 1);
        int p  = (j >> 7) & (BUDGET - 1);
        int b  = j >> 19;

        int ctx = *ctxp;
        int ql  = __ldg(&qlens[b]);
        const float4* row = resolve_row(cache, vnew, b, p, 1, ctx, ql, maxkv, seq_len)
                            + h * VEC_PER_ROW;
        float4 v0 = __ldg(&row[d4]);
        float4 v1 = __ldg(&row[d4 + 1]);
        float4* orow = out + out_row_base(b, p, 1, maxkv) + h * VEC_PER_ROW;
        __stwt(&orow[d4],     v0);
        __stwt(&orow[d4 + 1], v1);
    } else {
        // ---- identity region: 4 warp-contiguous units, MLP 4 ----
        int j = gid - nAV;
        int b = j >> id_shift;
        int w = j & id_mask;               // per-batch thread index
        long long base = ((long long)b * (maxkv / PAGE) + (BUDGET / PAGE))
                         * F4_PER_PAGE;
        // group of 128 f4 per 32 threads; thread owns lanes {0,32,64,96}+lane
        long long idx = base + (long long)(w >> 5) * 128 + (w & 31);
        float4 v0 = __ldg(&cache[idx]);
        float4 v1 = __ldg(&cache[idx + 32]);
        float4 v2 = __ldg(&cache[idx + 64]);
        float4 v3 = __ldg(&cache[idx + 96]);
        __stwt(&out[idx],      v0);
        __stwt(&out[idx + 32], v1);
        __stwt(&out[idx + 64], v2);
        __stwt(&out[idx + 96], v3);
    }
}

extern "C" void kernel_launch(void* const* d_in, const int* in_sizes, int n_in,
                              void* d_out, int out_size) {
    const float4* cache = (const float4*)d_in[0];
    const float4* knew  = (const float4*)d_in[1];
    const float4* vnew  = (const float4*)d_in[2];
    const int*    qlens = (const int*)d_in[3];
    const int*    ctxp  = (const int*)d_in[5];   // context_len scalar (device)

    int bsz = in_sizes[3];
    int total_pos = in_sizes[0] / (2 * HH * DD);
    int maxkv = total_pos / bsz;                 // 8192
    int seq_len = in_sizes[1] / (bsz * HH * DD); // 2048

    // Region sizes (threads)
    int nA  = bsz * BUDGET * HH * (VEC_PER_ROW / 2);   // rope pairs
    int nV  = bsz * BUDGET * HH * (VEC_PER_ROW / 2);   // value 32B units
    int nAV = nA + nV;

    int id_pages = maxkv / PAGE - BUDGET / PAGE;                 // per batch
    long long id_thr = (long long)id_pages * F4_PER_PAGE / 4;    // threads/batch (pow2)
    int id_shift = 0;
    while ((1LL << id_shift) < id_thr) id_shift++;
    int id_mask = (int)(id_thr - 1);

    int ntot = nAV + (int)(id_thr * bsz);
    int blocks = (ntot + 255) / 256;

    skv_fused<<<blocks, 256>>>(cache, knew, vnew, qlens, ctxp,
                               (float4*)d_out, maxkv, seq_len,
                               nA, nAV, id_shift, id_mask, ntot);
}

// round 17
// speedup vs baseline: 1.0542x; 1.0491x over previous
#include <cuda_runtime.h>
#include <math.h>

// Fixed geometry: D=128, H=8, PAGE_SIZE=16, STREAMING_BUDGET=4096, NUM_SINK=4.
#define DD      128
#define HH      8
#define PAGE    16
#define BUDGET  4096
#define SINK    4
#define VEC_PER_ROW (DD/4)            // 32 float4 per head-row
#define F4_PER_PAGE (2*PAGE*HH*DD/4)  // 8192 float4 per page (k half then v half)

// log2(10000)/64, double precision
#define LOG2_1E4_OVER_64 0.20762050593045952

// Source head-row pointer for the streaming-gather (kv = 0 keys / 1 values).
__device__ __forceinline__ const float4*
resolve_row(const float4* __restrict__ cache, const float4* __restrict__ fresh,
            int b, int p, int kv, int ctx, int ql, int maxkv, int seq_len)
{
    bool active  = (ql > 0);
    bool rolling = active && (ctx + ql >  BUDGET);
    bool plain   = active && (ctx + ql <= BUDGET);

    if (rolling && p >= SINK && p < BUDGET - ql) {
        int srs = min(ctx, BUDGET) - (BUDGET - ql - SINK);
        int pos = min(max(p + srs - SINK, 0), maxkv - 1);
        int gp  = b * maxkv + pos;
        return cache + (size_t)(gp >> 4) * F4_PER_PAGE
                     + (size_t)(kv * PAGE + (gp & 15)) * (HH * VEC_PER_ROW);
    }
    if ((rolling && p >= BUDGET - ql && p < BUDGET) ||
        (plain   && p >= ctx         && p < ctx + ql)) {
        int sp = rolling ? (p - (BUDGET - ql)) : (p - ctx);
        sp = min(max(sp, 0), seq_len - 1);
        return fresh + ((size_t)(b * seq_len + sp) * HH) * VEC_PER_ROW;
    }
    int gp = b * maxkv + p;
    return cache + (size_t)(gp >> 4) * F4_PER_PAGE
                 + (size_t)(kv * PAGE + (gp & 15)) * (HH * VEC_PER_ROW);
}

// Destination float4 base of position (b,p,kv) in the paged output (head 0).
__device__ __forceinline__ size_t out_row_base(int b, int p, int kv, int maxkv)
{
    int gp = b * maxkv + p;
    return (size_t)(gp >> 4) * F4_PER_PAGE
         + (size_t)(kv * PAGE + (gp & 15)) * (HH * VEC_PER_ROW);
}

// Fused single-launch kernel. Three equal-sized regions (8192 blocks each for
// the reference shape), INTERLEAVED across the grid so every scheduling wave
// carries a 1/3 mix of rope / value-gather / identity blocks:
//   region = blockIdx.x % 3, sub-block = blockIdx.x / 3.
//   region 0: rope'd keys, p<BUDGET. thread = float4 pair (d4, d4+16).
//   region 1: value gather, p<BUDGET. thread = 2 consecutive float4.
//   region 2: identity copy, p>=BUDGET: thread = 4 float4 at strides
//             {0,32,64,96} in a 128-f4 group -> warp-contiguous, MLP 4.
// Stores are write-through (__stwt): output is write-once, never re-read.
__global__ __launch_bounds__(256)
void skv_fused(const float4* __restrict__ cache,
               const float4* __restrict__ knew,
               const float4* __restrict__ vnew,
               const int*    __restrict__ qlens,
               const int*    __restrict__ ctxp,
               float4*       __restrict__ out,
               int maxkv, int seq_len,
               int nA, int nV,
               int id_shift, int id_mask, int nId)
{
    __shared__ float sfreq[DD/2];
    int tid = threadIdx.x;
    int region = blockIdx.x % 3;
    int rblk   = blockIdx.x / 3;
    int rid    = rblk * 256 + tid;       // thread index within region

    // Rope-region blocks build the inv_freq table in smem
    // (double exp2 -> correctly-rounded fp32, same values as a double pow).
    if (region == 0) {
        if (tid < DD/2)
            sfreq[tid] = (float)exp2(-(double)tid * LOG2_1E4_OVER_64);
        __syncthreads();
    }

    if (region == 0) {
        // ---- RoPE keys ----
        if (rid >= nA) return;
        int d4 = rid & 15;                 // lower-half float4 index (0..15)
        int h  = (rid >> 4) & (HH - 1);
        int p  = (rid >> 7) & (BUDGET - 1);
        int b  = rid >> 19;

        int ctx = *ctxp;
        int ql  = __ldg(&qlens[b]);

        const float4* row = resolve_row(cache, knew, b, p, 0, ctx, ql, maxkv, seq_len)
                            + h * VEC_PER_ROW;
        float4 x1 = __ldg(&row[d4]);
        float4 x2 = __ldg(&row[d4 + 16]);

        float fp = (float)p;
        int i0 = d4 * 4;
        float4 lo, hi;
        const float* a  = (const float*)&x1;
        const float* bb = (const float*)&x2;
        float* lf = (float*)&lo;
        float* hf = (float*)&hi;
        #pragma unroll
        for (int j = 0; j < 4; j++) {
            float s, c;
            __sincosf(fp * sfreq[i0 + j], &s, &c);   // MUFU fast path
            lf[j] = a[j] * c - bb[j] * s;
            hf[j] = a[j] * s + bb[j] * c;
        }

        float4* orow = out + out_row_base(b, p, 0, maxkv) + h * VEC_PER_ROW;
        __stwt(&orow[d4],      lo);
        __stwt(&orow[d4 + 16], hi);
    } else if (region == 1) {
        // ---- value gather, p < BUDGET ----
        if (rid >= nV) return;
        int d4 = (rid & 15) * 2;           // pair of consecutive float4
        int h  = (rid >> 4) & (HH - 1);
        int p  = (rid >> 7) & (BUDGET - 1);
        int b  = rid >> 19;

        int ctx = *ctxp;
        int ql  = __ldg(&qlens[b]);
        const float4* row = resolve_row(cache, vnew, b, p, 1, ctx, ql, maxkv, seq_len)
                            + h * VEC_PER_ROW;
        float4 v0 = __ldg(&row[d4]);
        float4 v1 = __ldg(&row[d4 + 1]);
        float4* orow = out + out_row_base(b, p, 1, maxkv) + h * VEC_PER_ROW;
        __stwt(&orow[d4],     v0);
        __stwt(&orow[d4 + 1], v1);
    } else {
        // ---- identity region: 4 warp-contiguous units, MLP 4 ----
        if (rid >= nId) return;
        int b = rid >> id_shift;
        int w = rid & id_mask;             // per-batch thread index
        long long base = ((long long)b * (maxkv / PAGE) + (BUDGET / PAGE))
                         * F4_PER_PAGE;
        // group of 128 f4 per 32 threads; thread owns lanes {0,32,64,96}+lane
        long long idx = base + (long long)(w >> 5) * 128 + (w & 31);
        float4 v0 = __ldg(&cache[idx]);
        float4 v1 = __ldg(&cache[idx + 32]);
        float4 v2 = __ldg(&cache[idx + 64]);
        float4 v3 = __ldg(&cache[idx + 96]);
        __stwt(&out[idx],      v0);
        __stwt(&out[idx + 32], v1);
        __stwt(&out[idx + 64], v2);
        __stwt(&out[idx + 96], v3);
    }
}

extern "C" void kernel_launch(void* const* d_in, const int* in_sizes, int n_in,
                              void* d_out, int out_size) {
    const float4* cache = (const float4*)d_in[0];
    const float4* knew  = (const float4*)d_in[1];
    const float4* vnew  = (const float4*)d_in[2];
    const int*    qlens = (const int*)d_in[3];
    const int*    ctxp  = (const int*)d_in[5];   // context_len scalar (device)

    int bsz = in_sizes[3];
    int total_pos = in_sizes[0] / (2 * HH * DD);
    int maxkv = total_pos / bsz;                 // 8192
    int seq_len = in_sizes[1] / (bsz * HH * DD); // 2048

    // Region sizes (threads)
    int nA = bsz * BUDGET * HH * (VEC_PER_ROW / 2);   // rope pairs
    int nV = bsz * BUDGET * HH * (VEC_PER_ROW / 2);   // value 32B units

    int id_pages = maxkv / PAGE - BUDGET / PAGE;                 // per batch
    long long id_thr = (long long)id_pages * F4_PER_PAGE / 4;    // threads/batch (pow2)
    int id_shift = 0;
    while ((1LL << id_shift) < id_thr) id_shift++;
    int id_mask = (int)(id_thr - 1);
    int nId = (int)(id_thr * bsz);

    // Interleaved grid: blocks for each region rounded up, then x3.
    int bA  = (nA  + 255) / 256;
    int bV  = (nV  + 255) / 256;
    int bId = (nId + 255) / 256;
    int bMax = bA > bV ? bA : bV;
    if (bId > bMax) bMax = bId;
    int blocks = bMax * 3;

    skv_fused<<<blocks, 256>>>(cache, knew, vnew, qlens, ctxp,
                               (float4*)d_out, maxkv, seq_len,
                               nA, nV, id_shift, id_mask, nId);
}